// round 3
// baseline (speedup 1.0000x reference)
#include <cuda_runtime.h>
#include <cstdint>

#define B_    32
#define IC_   16
#define OC_   16
#define KTOT  65536      // (M-1)*(N-1)
#define E_    131584     // edges
#define VOFF  65792      // M*(N-1)
#define KT    32         // k per tile (never crosses a 256-wide row)

__device__ __forceinline__ unsigned long long pack2(float lo, float hi) {
    unsigned long long r;
    asm("mov.b64 %0, {%1, %2};" : "=l"(r) : "f"(lo), "f"(hi));
    return r;
}
__device__ __forceinline__ void fma2(unsigned long long &acc,
                                     unsigned long long a, unsigned long long b) {
    asm("fma.rn.f32x2 %0, %1, %2, %0;" : "+l"(acc) : "l"(a), "l"(b));
}
__device__ __forceinline__ float2 unpack2(unsigned long long v) {
    float2 f;
    asm("mov.b64 {%0, %1}, %2;" : "=f"(f.x), "=f"(f.y) : "l"(v));
    return f;
}
__device__ __forceinline__ void cp_async16(unsigned dst, const void* src) {
    asm volatile("cp.async.cg.shared.global [%0], [%1], 16;\n"
                 :: "r"(dst), "l"(src) : "memory");
}
__device__ __forceinline__ void cp_commit() {
    asm volatile("cp.async.commit_group;\n" ::: "memory");
}
__device__ __forceinline__ void cp_wait_all() {
    asm volatile("cp.async.wait_group 0;\n" ::: "memory");
}

// Block: 32 k-lanes x 16 warps. y = oh*8 + bg (consumer role).
// Staging role: warp y loads x for batches {2y, 2y+1} into smem (no duplication).
// Block covers one 32-wide k-tile, all 32 batches, all 16 o-channels:
// weights stream from DRAM exactly once.
__global__ __launch_bounds__(512, 1)
void edges_kernel(const float* __restrict__ x,
                  const float4* __restrict__ w4,
                  const float* __restrict__ bias,
                  float* __restrict__ out)
{
    __shared__ float4 sw [2][16 * KT];      // weights [buf][o*32+klane]
    __shared__ float2 sxA[2][B_][KT];       // (x_t0, x_t1)   [buf][b][klane]
    __shared__ float2 sxB[2][B_][KT];       // (x_t2, x_t3)   [buf][b][klane]

    const int lane  = threadIdx.x;
    const int y     = threadIdx.y;
    const int oh    = y >> 3;
    const int bg    = y & 7;
    const int bbase = bg * 4;

    const int k0 = blockIdx.x * KT;
    const int k  = k0 + lane;
    const int i  = k0 >> 8;
    const int c2 = VOFF + i * 257 + (k0 & 255) + lane;   // t2 col; t3 = c2+1

    // weight cp.async mapping: 512 threads x 16B = one 8KB slab per ic
    const int tld = y * 32 + lane;
    const float4* wsrc = w4 + (size_t)((tld >> 5) * IC_) * KTOT + k0 + (tld & 31);
    unsigned swdst[2];
    swdst[0] = (unsigned)__cvta_generic_to_shared(&sw[0][tld]);
    swdst[1] = (unsigned)__cvta_generic_to_shared(&sw[1][tld]);

    // x staging: this warp owns batches 2y and 2y+1
    const float* xs0 = x + (size_t)((2 * y)     * IC_) * E_;
    const float* xs1 = x + (size_t)((2 * y + 1) * IC_) * E_;

    unsigned long long acc[8][4];
    #pragma unroll
    for (int oo = 0; oo < 8; ++oo)
        #pragma unroll
        for (int bb = 0; bb < 4; ++bb) acc[oo][bb] = 0ull;

    float a0[2], a1[2], a2[2], a3[2];

    // ---- prologue: ic = 0 ----
    cp_async16(swdst[0], wsrc);
    cp_commit();
    {
        const float* p0 = xs0; const float* p1 = xs1;
        a0[0]=__ldg(p0+k);     a0[1]=__ldg(p1+k);
        a1[0]=__ldg(p0+k+256); a1[1]=__ldg(p1+k+256);
        a2[0]=__ldg(p0+c2);    a2[1]=__ldg(p1+c2);
        a3[0]=(lane==31)?__ldg(p0+c2+1):0.f;
        a3[1]=(lane==31)?__ldg(p1+c2+1):0.f;
    }
    #pragma unroll
    for (int s = 0; s < 2; ++s) {
        float n = __shfl_down_sync(0xffffffffu, a2[s], 1);
        if (lane == 31) n = a3[s];
        sxA[0][2*y+s][lane] = make_float2(a0[s], a1[s]);
        sxB[0][2*y+s][lane] = make_float2(a2[s], n);
    }
    cp_wait_all();
    __syncthreads();

    int buf = 0;
    #pragma unroll 1
    for (int ic = 0; ic < IC_; ++ic) {
        // kick off next ic's weight slab + x gathers
        if (ic < IC_ - 1) {
            cp_async16(swdst[buf ^ 1], wsrc + (size_t)(ic + 1) * KTOT);
            cp_commit();
            const float* p0 = xs0 + (size_t)(ic + 1) * E_;
            const float* p1 = xs1 + (size_t)(ic + 1) * E_;
            a0[0]=__ldg(p0+k);     a0[1]=__ldg(p1+k);
            a1[0]=__ldg(p0+k+256); a1[1]=__ldg(p1+k+256);
            a2[0]=__ldg(p0+c2);    a2[1]=__ldg(p1+c2);
            a3[0]=(lane==31)?__ldg(p0+c2+1):0.f;
            a3[1]=(lane==31)?__ldg(p1+c2+1):0.f;
        }

        // consume current buffer
        unsigned long long xA[4], xB[4];
        #pragma unroll
        for (int bb = 0; bb < 4; ++bb) {
            xA[bb] = *reinterpret_cast<const unsigned long long*>(&sxA[buf][bbase+bb][lane]);
            xB[bb] = *reinterpret_cast<const unsigned long long*>(&sxB[buf][bbase+bb][lane]);
        }
        const float4* swrow = &sw[buf][(oh * 8) * KT + lane];
        #pragma unroll
        for (int oo = 0; oo < 8; ++oo) {
            unsigned long long wA, wB;
            unsigned sa = (unsigned)__cvta_generic_to_shared(swrow + oo * KT);
            asm("ld.shared.v2.u64 {%0, %1}, [%2];" : "=l"(wA), "=l"(wB) : "r"(sa));
            #pragma unroll
            for (int bb = 0; bb < 4; ++bb) {
                fma2(acc[oo][bb], wA, xA[bb]);
                fma2(acc[oo][bb], wB, xB[bb]);
            }
        }

        if (ic < IC_ - 1) {
            #pragma unroll
            for (int s = 0; s < 2; ++s) {
                float n = __shfl_down_sync(0xffffffffu, a2[s], 1);
                if (lane == 31) n = a3[s];
                sxA[buf ^ 1][2*y+s][lane] = make_float2(a0[s], a1[s]);
                sxB[buf ^ 1][2*y+s][lane] = make_float2(a2[s], n);
            }
            cp_wait_all();
            __syncthreads();
            buf ^= 1;
        }
    }

    // epilogue: lo+hi + bias, coalesced STG.32
    #pragma unroll
    for (int oo = 0; oo < 8; ++oo) {
        const int o = oh * 8 + oo;
        const float bo = __ldg(&bias[o]);
        #pragma unroll
        for (int bb = 0; bb < 4; ++bb) {
            float2 v = unpack2(acc[oo][bb]);
            out[(size_t)((bbase + bb) * OC_ + o) * KTOT + k] = v.x + v.y + bo;
        }
    }
}

extern "C" void kernel_launch(void* const* d_in, const int* in_sizes, int n_in,
                              void* d_out, int out_size)
{
    const float*  x    = (const float*)d_in[0];
    const float4* w4   = (const float4*)d_in[1];
    const float*  bias = (const float*)d_in[2];
    float*        out  = (float*)d_out;

    dim3 block(32, 16);
    dim3 grid(KTOT / KT);
    edges_kernel<<<grid, block>>>(x, w4, bias, out);
}

// round 4
// speedup vs baseline: 1.2203x; 1.2203x over previous
#include <cuda_runtime.h>
#include <cstdint>

#define B_    32
#define IC_   16
#define OC_   16
#define KTOT  65536      // (M-1)*(N-1)
#define E_    131584     // edges
#define VOFF  65792      // M*(N-1)
#define KT    32         // k per tile (never crosses a 256-wide row)
#define NBUF  4          // weight pipeline depth

__device__ __forceinline__ unsigned long long pack2(float lo, float hi) {
    unsigned long long r;
    asm("mov.b64 %0, {%1, %2};" : "=l"(r) : "f"(lo), "f"(hi));
    return r;
}
__device__ __forceinline__ void fma2(unsigned long long &acc,
                                     unsigned long long a, unsigned long long b) {
    asm("fma.rn.f32x2 %0, %1, %2, %0;" : "+l"(acc) : "l"(a), "l"(b));
}
__device__ __forceinline__ float2 unpack2(unsigned long long v) {
    float2 f;
    asm("mov.b64 {%0, %1}, %2;" : "=f"(f.x), "=f"(f.y) : "l"(v));
    return f;
}
__device__ __forceinline__ void cp_async16(unsigned dst, const void* src) {
    asm volatile("cp.async.cg.shared.global [%0], [%1], 16;\n"
                 :: "r"(dst), "l"(src) : "memory");
}
__device__ __forceinline__ void cp_commit() {
    asm volatile("cp.async.commit_group;\n" ::: "memory");
}
template<int N>
__device__ __forceinline__ void cp_wait() {
    asm volatile("cp.async.wait_group %0;\n" :: "n"(N) : "memory");
}

// Block: 32 k-lanes x 16 warps. y = oh*8 + bg.
// Block covers one 32-wide k tile, all 32 batches, all 16 o-channels
// => every weight element read from DRAM exactly once.
__global__ __launch_bounds__(512, 1)
void edges_kernel(const float* __restrict__ x,
                  const float4* __restrict__ w4,
                  const float* __restrict__ bias,
                  float* __restrict__ out)
{
    __shared__ float4 sw[NBUF][16 * KT];   // [buf][o*32 + klocal] = w[o,ic,k,0..3]

    const int lane = threadIdx.x;
    const int y    = threadIdx.y;
    const int oh   = y >> 3;
    const int bg   = y & 7;
    const int bbase = bg * 4;

    const int k0 = blockIdx.x * KT;
    const int k  = k0 + lane;
    const int i  = k0 >> 8;
    const int c0 = k;                              // t0; t1 = c0+256
    const int c2 = VOFF + i * 257 + (k0 & 255) + lane;  // t2; t3 = c2+1

    // cooperative weight copy: 512 threads x 16B = 8 KB slab per ic
    const int tld = y * 32 + lane;
    const float4* wsrc = w4 + (size_t)((tld >> 5) * IC_) * KTOT + k0 + (tld & 31);
    unsigned swdst[NBUF];
    #pragma unroll
    for (int s = 0; s < NBUF; ++s)
        swdst[s] = (unsigned)__cvta_generic_to_shared(&sw[s][tld]);

    const float* xp[4];
    #pragma unroll
    for (int bb = 0; bb < 4; ++bb)
        xp[bb] = x + (size_t)((bbase + bb) * IC_) * E_;

    unsigned long long acc[8][4];
    #pragma unroll
    for (int oo = 0; oo < 8; ++oo)
        #pragma unroll
        for (int bb = 0; bb < 4; ++bb) acc[oo][bb] = 0ull;

    // ---- prologue: launch weight stages 0..2, gather x for ic=0 ----
    #pragma unroll
    for (int s = 0; s < 3; ++s) {
        cp_async16(swdst[s], wsrc + (size_t)s * KTOT);
        cp_commit();
    }

    float xf[4][4];
    #pragma unroll
    for (int bb = 0; bb < 4; ++bb) {
        const float* xb = xp[bb];
        xf[bb][0] = __ldg(xb + c0);
        xf[bb][1] = __ldg(xb + c0 + 256);
        xf[bb][2] = __ldg(xb + c2);
        xf[bb][3] = __ldg(xb + c2 + 1);
    }

    #pragma unroll 1
    for (int ic = 0; ic < IC_; ++ic) {
        // wait until weight stage `ic` has landed (keep up to 2 younger in flight)
        if (ic <= IC_ - 3)      cp_wait<2>();
        else if (ic == IC_ - 2) cp_wait<1>();
        else                    cp_wait<0>();
        __syncthreads();   // slab visible to all; prev readers of buf (ic-1)&3 done

        // launch weight stage ic+3 (reuses buffer freed by iter ic-1)
        if (ic + 3 < IC_) {
            cp_async16(swdst[(ic + 3) & (NBUF - 1)], wsrc + (size_t)(ic + 3) * KTOT);
            cp_commit();
        }

        // pack current x
        unsigned long long xA[4], xB[4];
        #pragma unroll
        for (int bb = 0; bb < 4; ++bb) {
            xA[bb] = pack2(xf[bb][0], xf[bb][1]);
            xB[bb] = pack2(xf[bb][2], xf[bb][3]);
        }

        // prefetch x for ic+1 under this iteration's FMAs
        if (ic < IC_ - 1) {
            const int off = (ic + 1) * E_;
            #pragma unroll
            for (int bb = 0; bb < 4; ++bb) {
                const float* xb = xp[bb] + off;
                xf[bb][0] = __ldg(xb + c0);
                xf[bb][1] = __ldg(xb + c0 + 256);
                xf[bb][2] = __ldg(xb + c2);
                xf[bb][3] = __ldg(xb + c2 + 1);
            }
        }

        // compute: 8 o x 4 b x 2 fma2
        const float4* swrow = &sw[ic & (NBUF - 1)][(oh * 8) * KT + lane];
        #pragma unroll
        for (int oo = 0; oo < 8; ++oo) {
            unsigned long long wA, wB;
            unsigned sa = (unsigned)__cvta_generic_to_shared(swrow + oo * KT);
            asm("ld.shared.v2.u64 {%0, %1}, [%2];" : "=l"(wA), "=l"(wB) : "r"(sa));
            #pragma unroll
            for (int bb = 0; bb < 4; ++bb) {
                fma2(acc[oo][bb], wA, xA[bb]);
                fma2(acc[oo][bb], wB, xB[bb]);
            }
        }
    }

    // epilogue: lo+hi + bias, coalesced STG.32
    #pragma unroll
    for (int oo = 0; oo < 8; ++oo) {
        const int o = oh * 8 + oo;
        const float bo = __ldg(&bias[o]);
        #pragma unroll
        for (int bb = 0; bb < 4; ++bb) {
            float2 v = unpack2(acc[oo][bb]);
            out[(size_t)((bbase + bb) * OC_ + o) * KTOT + k] = v.x + v.y + bo;
        }
    }
}

extern "C" void kernel_launch(void* const* d_in, const int* in_sizes, int n_in,
                              void* d_out, int out_size)
{
    const float*  x    = (const float*)d_in[0];
    const float4* w4   = (const float4*)d_in[1];
    const float*  bias = (const float*)d_in[2];
    float*        out  = (float*)d_out;

    dim3 block(32, 16);
    dim3 grid(KTOT / KT);
    edges_kernel<<<grid, block>>>(x, w4, bias, out);
}